// round 1
// baseline (speedup 1.0000x reference)
#include <cuda_runtime.h>

namespace {
constexpr int C   = 64;    // input channels
constexpr int H   = 448;   // rows (= conv groups)
constexpr int W   = 608;   // width
constexpr int K   = 32;    // classes per row
constexpr int B   = 2;     // batch
constexpr int TPB = 128;   // threads per block (pixels per tile)
constexpr int WT  = (W + TPB - 1) / TPB;  // 5 w-tiles
// smem: W1(4096) + W2(4096) + W3(2048) + b1(64) + b2(64) + b3(32) + x-stash(C*TPB)
constexpr int SMEM_FLOATS = 4096 + 4096 + 2048 + 64 + 64 + 32 + C * TPB;
}

__device__ __forceinline__ float lrelu(float v) { return v >= 0.0f ? v : 0.01f * v; }

__global__ void __launch_bounds__(TPB, 3)
reg1stage_kernel(const float* __restrict__ x,
                 const float* __restrict__ W1g, const float* __restrict__ b1g,
                 const float* __restrict__ W2g, const float* __restrict__ b2g,
                 const float* __restrict__ W3g, const float* __restrict__ b3g,
                 const float* __restrict__ Wr,  const float* __restrict__ br,
                 float* __restrict__ out)
{
    extern __shared__ float smem[];
    const int h   = blockIdx.x;
    const int b   = blockIdx.y;
    const int tid = threadIdx.x;

    float* sW1 = smem;           // [64][64] row-major (o, c)
    float* sW2 = sW1 + 4096;
    float* sW3 = sW2 + 4096;     // [32][64]
    float* sb1 = sW3 + 2048;
    float* sb2 = sb1 + 64;
    float* sb3 = sb2 + 64;
    float* sx  = sb3 + 32;       // [C][TPB] per-thread x stash

    // ---- stage weights for this row h into shared memory (vectorized) ----
    {
        const float4* g1 = reinterpret_cast<const float4*>(W1g + h * 4096);
        float4*       s1 = reinterpret_cast<float4*>(sW1);
        #pragma unroll
        for (int i = 0; i < 8; ++i) s1[tid + i * TPB] = g1[tid + i * TPB];
        const float4* g2 = reinterpret_cast<const float4*>(W2g + h * 4096);
        float4*       s2 = reinterpret_cast<float4*>(sW2);
        #pragma unroll
        for (int i = 0; i < 8; ++i) s2[tid + i * TPB] = g2[tid + i * TPB];
        const float4* g3 = reinterpret_cast<const float4*>(W3g + h * 2048);
        float4*       s3 = reinterpret_cast<float4*>(sW3);
        #pragma unroll
        for (int i = 0; i < 4; ++i) s3[tid + i * TPB] = g3[tid + i * TPB];
        if (tid < 64) {
            sb1[tid] = b1g[h * 64 + tid];
            sb2[tid] = b2g[h * 64 + tid];
        } else if (tid < 96) {
            sb3[tid - 64] = b3g[h * 32 + (tid - 64)];
        }
    }
    __syncthreads();

    const int cstride = H * W;                       // stride between channels in x
    const float* xbase = x + b * C * cstride + h * W;
    const float inv_k = 1.0f / (float)K;
    const int pix_base = (b * H + h) * W;
    const int plane = B * H * W;                     // offset of mask plane in out

    for (int wt = 0; wt < WT; ++wt) {
        const int w = wt * TPB + tid;
        if (w < W) {
            // ---- load x column: coalesced across lanes, once from HBM ----
            float xr[C];
            #pragma unroll
            for (int c = 0; c < C; ++c) {
                float v = __ldg(xbase + c * cstride + w);
                xr[c] = v;
                sx[c * TPB + tid] = v;               // stash for cond-mul gather
            }

            // ---- layer 1: a1 = lrelu(W1 @ x + b1) ----
            float a1[C];
            #pragma unroll
            for (int og = 0; og < C / 8; ++og) {
                float acc[8];
                #pragma unroll
                for (int j = 0; j < 8; ++j) acc[j] = sb1[og * 8 + j];
                #pragma unroll
                for (int c = 0; c < C; c += 4) {
                    #pragma unroll
                    for (int j = 0; j < 8; ++j) {
                        const float4 wv = *reinterpret_cast<const float4*>(sW1 + (og * 8 + j) * C + c);
                        acc[j] = fmaf(wv.x, xr[c + 0], acc[j]);
                        acc[j] = fmaf(wv.y, xr[c + 1], acc[j]);
                        acc[j] = fmaf(wv.z, xr[c + 2], acc[j]);
                        acc[j] = fmaf(wv.w, xr[c + 3], acc[j]);
                    }
                }
                #pragma unroll
                for (int j = 0; j < 8; ++j) a1[og * 8 + j] = lrelu(acc[j]);
            }

            // ---- layer 2: a2 = lrelu(W2 @ a1 + b2) ----
            float a2[C];
            #pragma unroll
            for (int og = 0; og < C / 8; ++og) {
                float acc[8];
                #pragma unroll
                for (int j = 0; j < 8; ++j) acc[j] = sb2[og * 8 + j];
                #pragma unroll
                for (int c = 0; c < C; c += 4) {
                    #pragma unroll
                    for (int j = 0; j < 8; ++j) {
                        const float4 wv = *reinterpret_cast<const float4*>(sW2 + (og * 8 + j) * C + c);
                        acc[j] = fmaf(wv.x, a1[c + 0], acc[j]);
                        acc[j] = fmaf(wv.y, a1[c + 1], acc[j]);
                        acc[j] = fmaf(wv.z, a1[c + 2], acc[j]);
                        acc[j] = fmaf(wv.w, a1[c + 3], acc[j]);
                    }
                }
                #pragma unroll
                for (int j = 0; j < 8; ++j) a2[og * 8 + j] = lrelu(acc[j]);
            }

            // ---- layer 3 + argmax (first-max semantics, lrelu before compare) ----
            float best = -3.402823466e38f;
            int bk = 0;
            #pragma unroll
            for (int kg = 0; kg < K / 8; ++kg) {
                float acc[8];
                #pragma unroll
                for (int j = 0; j < 8; ++j) acc[j] = sb3[kg * 8 + j];
                #pragma unroll
                for (int c = 0; c < C; c += 4) {
                    #pragma unroll
                    for (int j = 0; j < 8; ++j) {
                        const float4 wv = *reinterpret_cast<const float4*>(sW3 + (kg * 8 + j) * C + c);
                        acc[j] = fmaf(wv.x, a2[c + 0], acc[j]);
                        acc[j] = fmaf(wv.y, a2[c + 1], acc[j]);
                        acc[j] = fmaf(wv.z, a2[c + 2], acc[j]);
                        acc[j] = fmaf(wv.w, a2[c + 3], acc[j]);
                    }
                }
                #pragma unroll
                for (int j = 0; j < 8; ++j) {            // ascending k, strict > keeps first max
                    float s = lrelu(acc[j]);
                    if (s > best) { best = s; bk = kg * 8 + j; }
                }
            }

            // ---- class-conditioned linear on original x ----
            const int flat = h * K + bk;
            const float2* wr = reinterpret_cast<const float2*>(Wr + (size_t)flat * (C * 2));
            float r0 = 0.0f, r1 = 0.0f;
            #pragma unroll
            for (int c = 0; c < C; ++c) {
                const float  xv = sx[c * TPB + tid];
                const float2 wv = __ldg(wr + c);
                r0 = fmaf(xv, wv.x, r0);
                r1 = fmaf(xv, wv.y, r1);
            }
            const float2 bv = __ldg(reinterpret_cast<const float2*>(br) + flat);
            const float reg0 = lrelu(r0 + bv.x);
            const float reg1 = lrelu(r1 + bv.y);

            const int pix = pix_base + w;
            out[pix]         = ((float)flat + reg0) * inv_k;   // xpos
            out[plane + pix] = lrelu(reg1);                    // mask (double lrelu per ref)
        }
    }
}

extern "C" void kernel_launch(void* const* d_in, const int* in_sizes, int n_in,
                              void* d_out, int out_size)
{
    const float* x  = (const float*)d_in[0];
    const float* W1 = (const float*)d_in[1];
    const float* b1 = (const float*)d_in[2];
    const float* W2 = (const float*)d_in[3];
    const float* b2 = (const float*)d_in[4];
    const float* W3 = (const float*)d_in[5];
    const float* b3 = (const float*)d_in[6];
    const float* Wr = (const float*)d_in[7];
    const float* br = (const float*)d_in[8];
    float* out = (float*)d_out;

    const size_t smem_bytes = (size_t)SMEM_FLOATS * sizeof(float);  // 74368 B
    cudaFuncSetAttribute(reg1stage_kernel,
                         cudaFuncAttributeMaxDynamicSharedMemorySize, (int)smem_bytes);

    dim3 grid(H, B);   // one CTA per (row, batch); 5 w-tiles inside
    reg1stage_kernel<<<grid, TPB, smem_bytes>>>(x, W1, b1, W2, b2, W3, b3, Wr, br, out);
}

// round 2
// speedup vs baseline: 1.4024x; 1.4024x over previous
#include <cuda_runtime.h>

namespace {
constexpr int C   = 64;
constexpr int H   = 448;
constexpr int W   = 608;
constexpr int K   = 32;
constexpr int B   = 2;
constexpr int TPB = 128;
constexpr int PXT = 128;                 // pixels per tile
constexpr int WT  = (W + PXT - 1) / PXT; // 5 tiles

constexpr int WS12 = 68;  // padded row stride (floats) for transposed W1/W2 [k][o]
constexpr int WS3  = 36;  // padded row stride for transposed W3 [k][o]

constexpr int OFF_W1T = 0;
constexpr int OFF_W2T = OFF_W1T + 64 * WS12;       // 4352
constexpr int OFF_W3T = OFF_W2T + 64 * WS12;       // 8704
constexpr int OFF_B1  = OFF_W3T + 64 * WS3;        // 11008
constexpr int OFF_B2  = OFF_B1 + 64;
constexpr int OFF_B3  = OFF_B2 + 64;
constexpr int OFF_SX  = OFF_B3 + 32;               // 11168
constexpr int OFF_SY  = OFF_SX + C * PXT;          // 19360
constexpr int SMEM_FLOATS = OFF_SY + C * PXT;      // 27552 -> 110208 B
}

__device__ __forceinline__ float lrelu(float v) { return v >= 0.0f ? v : 0.01f * v; }

__device__ __forceinline__ unsigned long long pack_dup(float w) {
    unsigned long long r;
    asm("mov.b64 %0, {%1, %1};" : "=l"(r) : "f"(w));
    return r;
}
__device__ __forceinline__ void ffma2(unsigned long long& d, unsigned long long a, unsigned long long b) {
    asm("fma.rn.f32x2 %0, %1, %2, %0;" : "+l"(d) : "l"(a), "l"(b));
}
__device__ __forceinline__ void unpack2(unsigned long long p, float& lo, float& hi) {
    asm("mov.b64 {%0, %1}, %2;" : "=f"(lo), "=f"(hi) : "l"(p));
}

// Register-tiled GEMM over K=64: OUT_PER_T outputs x 8 pixels per thread.
// acc lanes = adjacent pixel pairs (f32x2).
template<int OUT_PER_T>
__device__ __forceinline__ void gemm_ffma2(const float* __restrict__ sWt, int ws,
                                           const float* __restrict__ sIn,
                                           int og, int pg,
                                           unsigned long long acc[OUT_PER_T][4])
{
    #pragma unroll
    for (int o = 0; o < OUT_PER_T; ++o)
        #pragma unroll
        for (int q = 0; q < 4; ++q) acc[o][q] = 0ull;

    const float* wbase = sWt + og * OUT_PER_T;
    const float* xbase = sIn + pg * 8;

    #pragma unroll 4
    for (int k = 0; k < 64; ++k) {
        const ulonglong2 xa = *reinterpret_cast<const ulonglong2*>(xbase + k * PXT);
        const ulonglong2 xb = *reinterpret_cast<const ulonglong2*>(xbase + k * PXT + 4);
        unsigned long long xp0 = xa.x, xp1 = xa.y, xp2 = xb.x, xp3 = xb.y;

        if (OUT_PER_T == 8) {
            const float4 w0 = *reinterpret_cast<const float4*>(wbase + k * ws);
            const float4 w1 = *reinterpret_cast<const float4*>(wbase + k * ws + 4);
            float wv[8] = {w0.x, w0.y, w0.z, w0.w, w1.x, w1.y, w1.z, w1.w};
            #pragma unroll
            for (int o = 0; o < 8; ++o) {
                unsigned long long wp = pack_dup(wv[o]);
                ffma2(acc[o][0], wp, xp0);
                ffma2(acc[o][1], wp, xp1);
                ffma2(acc[o][2], wp, xp2);
                ffma2(acc[o][3], wp, xp3);
            }
        } else {
            const float4 w0 = *reinterpret_cast<const float4*>(wbase + k * ws);
            float wv[4] = {w0.x, w0.y, w0.z, w0.w};
            #pragma unroll
            for (int o = 0; o < OUT_PER_T; ++o) {
                unsigned long long wp = pack_dup(wv[o]);
                ffma2(acc[o][0], wp, xp0);
                ffma2(acc[o][1], wp, xp1);
                ffma2(acc[o][2], wp, xp2);
                ffma2(acc[o][3], wp, xp3);
            }
        }
    }
}

// Epilogue: add bias, optional lrelu, store 8 pixels per output row to sOut.
template<int OUT_PER_T, bool DO_LRELU>
__device__ __forceinline__ void epilogue_store(unsigned long long acc[OUT_PER_T][4],
                                               const float* __restrict__ sb,
                                               float* __restrict__ sOut,
                                               int og, int pg)
{
    #pragma unroll
    for (int o = 0; o < OUT_PER_T; ++o) {
        const int orow = og * OUT_PER_T + o;
        const float bv = sb[orow];
        float v[8];
        #pragma unroll
        for (int q = 0; q < 4; ++q) {
            float lo, hi;
            unpack2(acc[o][q], lo, hi);
            lo += bv; hi += bv;
            if (DO_LRELU) { lo = lrelu(lo); hi = lrelu(hi); }
            v[2 * q] = lo; v[2 * q + 1] = hi;
        }
        float4* dst = reinterpret_cast<float4*>(sOut + orow * PXT + pg * 8);
        dst[0] = make_float4(v[0], v[1], v[2], v[3]);
        dst[1] = make_float4(v[4], v[5], v[6], v[7]);
    }
}

__global__ void __launch_bounds__(TPB, 2)
reg1stage_kernel(const float* __restrict__ x,
                 const float* __restrict__ W1g, const float* __restrict__ b1g,
                 const float* __restrict__ W2g, const float* __restrict__ b2g,
                 const float* __restrict__ W3g, const float* __restrict__ b3g,
                 const float* __restrict__ Wr,  const float* __restrict__ br,
                 float* __restrict__ out)
{
    extern __shared__ float smem[];
    const int h   = blockIdx.x;
    const int b   = blockIdx.y;
    const int tid = threadIdx.x;

    float* sW1t = smem + OFF_W1T;   // [k][o], stride WS12
    float* sW2t = smem + OFF_W2T;
    float* sW3t = smem + OFF_W3T;   // [k][o], stride WS3
    float* sb1  = smem + OFF_B1;
    float* sb2  = smem + OFF_B2;
    float* sb3  = smem + OFF_B3;
    float* sx   = smem + OFF_SX;    // [C][PXT]
    float* sy   = smem + OFF_SY;    // [64][PXT] reused Y1 -> Y2 -> cls

    // ---- stage transposed weights + biases for this row h ----
    {
        const float* g1 = W1g + h * 4096;
        const float* g2 = W2g + h * 4096;
        #pragma unroll
        for (int i = 0; i < 32; ++i) {
            const int idx = tid + i * TPB;            // 4096 elems
            const int o = idx >> 6, c = idx & 63;
            sW1t[c * WS12 + o] = g1[idx];
            sW2t[c * WS12 + o] = g2[idx];
        }
        const float* g3 = W3g + h * 2048;
        #pragma unroll
        for (int i = 0; i < 16; ++i) {
            const int idx = tid + i * TPB;            // 2048 elems
            const int ko = idx >> 6, c = idx & 63;
            sW3t[c * WS3 + ko] = g3[idx];
        }
        if (tid < 64) {
            sb1[tid] = b1g[h * 64 + tid];
            sb2[tid] = b2g[h * 64 + tid];
        }
        if (tid < 32) sb3[tid] = b3g[h * 32 + tid];
    }

    const int cstride = H * W;
    const float* xbase = x + b * C * cstride + h * W;
    const float inv_k = 1.0f / (float)K;
    const int pix_base = (b * H + h) * W;
    const int plane = B * H * W;

    const int og  = tid >> 4;       // 8 output groups (x8 outputs)
    const int og3 = tid >> 4;       // 8 groups (x4 outputs) for layer 3
    const int pg  = tid & 15;       // 16 pixel groups (x8 pixels)

    for (int wt = 0; wt < WT; ++wt) {
        const int w0 = wt * PXT;
        __syncthreads();            // prev tile fully consumed (sx/sy readers done)

        // ---- stage x tile [C][PXT], coalesced; clamp tail ----
        {
            const int w = min(w0 + tid, W - 1);
            #pragma unroll
            for (int c = 0; c < C; ++c)
                sx[c * PXT + tid] = __ldg(xbase + c * cstride + w);
        }
        __syncthreads();

        // ---- layer 1: Y1 = lrelu(W1 @ X + b1) -> sy ----
        {
            unsigned long long acc[8][4];
            gemm_ffma2<8>(sW1t, WS12, sx, og, pg, acc);
            epilogue_store<8, true>(acc, sb1, sy, og, pg);
        }
        __syncthreads();

        // ---- layer 2: Y2 = lrelu(W2 @ Y1 + b2) -> sy (in-place after full read) ----
        {
            unsigned long long acc[8][4];
            gemm_ffma2<8>(sW2t, WS12, sy, og, pg, acc);
            __syncthreads();
            epilogue_store<8, true>(acc, sb2, sy, og, pg);
        }
        __syncthreads();

        // ---- layer 3: cls = W3 @ Y2 + b3 -> sy rows [0,32) (lrelu skipped: monotone) ----
        {
            unsigned long long acc[4][4];
            gemm_ffma2<4>(sW3t, WS3, sy, og3, pg, acc);
            __syncthreads();
            epilogue_store<4, false>(acc, sb3, sy, og3, pg);
        }
        __syncthreads();

        // ---- per-pixel argmax + class-conditioned linear ----
        const int w = w0 + tid;
        if (w < W) {
            float best = -3.402823466e38f;
            int bk = 0;
            #pragma unroll
            for (int k = 0; k < K; ++k) {            // ascending, strict > => first max
                const float s = sy[k * PXT + tid];
                if (s > best) { best = s; bk = k; }
            }

            const int flat = h * K + bk;
            const float2* wr = reinterpret_cast<const float2*>(Wr + (size_t)flat * (C * 2));
            float r0 = 0.0f, r1 = 0.0f;
            #pragma unroll
            for (int c = 0; c < C; ++c) {
                const float  xv = sx[c * PXT + tid];
                const float2 wv = __ldg(wr + c);
                r0 = fmaf(xv, wv.x, r0);
                r1 = fmaf(xv, wv.y, r1);
            }
            const float2 bv = __ldg(reinterpret_cast<const float2*>(br) + flat);
            const float reg0 = lrelu(r0 + bv.x);
            const float reg1 = lrelu(r1 + bv.y);

            const int pix = pix_base + w;
            out[pix]         = ((float)flat + reg0) * inv_k;
            out[plane + pix] = lrelu(reg1);
        }
    }
}

extern "C" void kernel_launch(void* const* d_in, const int* in_sizes, int n_in,
                              void* d_out, int out_size)
{
    const float* x  = (const float*)d_in[0];
    const float* W1 = (const float*)d_in[1];
    const float* b1 = (const float*)d_in[2];
    const float* W2 = (const float*)d_in[3];
    const float* b2 = (const float*)d_in[4];
    const float* W3 = (const float*)d_in[5];
    const float* b3 = (const float*)d_in[6];
    const float* Wr = (const float*)d_in[7];
    const float* br = (const float*)d_in[8];
    float* out = (float*)d_out;

    const size_t smem_bytes = (size_t)SMEM_FLOATS * sizeof(float);  // 110208 B
    cudaFuncSetAttribute(reg1stage_kernel,
                         cudaFuncAttributeMaxDynamicSharedMemorySize, (int)smem_bytes);

    dim3 grid(H, B);
    reg1stage_kernel<<<grid, TPB, smem_bytes>>>(x, W1, b1, W2, b2, W3, b3, Wr, br, out);
}

// round 4
// speedup vs baseline: 1.4549x; 1.0374x over previous
#include <cuda_runtime.h>

namespace {
constexpr int C   = 64;
constexpr int H   = 448;
constexpr int W   = 608;
constexpr int K   = 32;
constexpr int B   = 2;
constexpr int TPB = 256;
constexpr int PXT = 128;                 // pixels per tile
constexpr int WT  = (W + PXT - 1) / PXT; // 5 tiles

constexpr int WS12 = 68;  // padded row stride (floats) for transposed W1/W2 [k][o]
constexpr int WS3  = 36;  // padded row stride for transposed W3 [k][o]

constexpr int OFF_W1T = 0;
constexpr int OFF_W2T = OFF_W1T + 64 * WS12;
constexpr int OFF_W3T = OFF_W2T + 64 * WS12;
constexpr int OFF_B1  = OFF_W3T + 64 * WS3;
constexpr int OFF_B2  = OFF_B1 + 64;
constexpr int OFF_B3  = OFF_B2 + 64;
constexpr int OFF_SX  = OFF_B3 + 32;
constexpr int OFF_SY  = OFF_SX + C * PXT;
constexpr int SMEM_FLOATS = OFF_SY + C * PXT;      // 27552 floats = 110208 B
}

__device__ __forceinline__ float lrelu(float v) { return v >= 0.0f ? v : 0.01f * v; }

__device__ __forceinline__ unsigned long long pack_dup(float w) {
    unsigned long long r;
    asm("mov.b64 %0, {%1, %1};" : "=l"(r) : "f"(w));
    return r;
}
__device__ __forceinline__ void ffma2(unsigned long long& d, unsigned long long a, unsigned long long b) {
    asm("fma.rn.f32x2 %0, %1, %2, %0;" : "+l"(d) : "l"(a), "l"(b));
}
__device__ __forceinline__ void unpack2(unsigned long long p, float& lo, float& hi) {
    asm("mov.b64 {%0, %1}, %2;" : "=f"(lo), "=f"(hi) : "l"(p));
}

// Per-thread tile: OUT_PER_T outputs x 4 pixels (2 f32x2 pairs).
// Warp owns 16 pixels x all outputs: lane = og(3b) | pq(2b).
template<int OUT_PER_T>
__device__ __forceinline__ void gemm_ffma2(const float* __restrict__ sWt, int ws,
                                           const float* __restrict__ sIn,
                                           int og, int pixoff,
                                           unsigned long long acc[OUT_PER_T][2])
{
    #pragma unroll
    for (int o = 0; o < OUT_PER_T; ++o) { acc[o][0] = 0ull; acc[o][1] = 0ull; }

    const float* wbase = sWt + og * OUT_PER_T;
    const float* xbase = sIn + pixoff;

    #pragma unroll 8
    for (int k = 0; k < 64; ++k) {
        const ulonglong2 xv = *reinterpret_cast<const ulonglong2*>(xbase + k * PXT);
        const unsigned long long x0 = xv.x, x1 = xv.y;

        if (OUT_PER_T == 8) {
            const float4 w0 = *reinterpret_cast<const float4*>(wbase + k * ws);
            const float4 w1 = *reinterpret_cast<const float4*>(wbase + k * ws + 4);
            const float wv[8] = {w0.x, w0.y, w0.z, w0.w, w1.x, w1.y, w1.z, w1.w};
            #pragma unroll
            for (int o = 0; o < 8; ++o) {
                const unsigned long long wp = pack_dup(wv[o]);
                ffma2(acc[o][0], wp, x0);
                ffma2(acc[o][1], wp, x1);
            }
        } else {
            const float4 w0 = *reinterpret_cast<const float4*>(wbase + k * ws);
            const float wv[4] = {w0.x, w0.y, w0.z, w0.w};
            #pragma unroll
            for (int o = 0; o < OUT_PER_T; ++o) {
                const unsigned long long wp = pack_dup(wv[o]);
                ffma2(acc[o][0], wp, x0);
                ffma2(acc[o][1], wp, x1);
            }
        }
    }
}

template<int OUT_PER_T, bool DO_LRELU>
__device__ __forceinline__ void epilogue_store(unsigned long long acc[OUT_PER_T][2],
                                               const float* __restrict__ sb,
                                               float* __restrict__ sOut,
                                               int og, int pixoff)
{
    #pragma unroll
    for (int o = 0; o < OUT_PER_T; ++o) {
        const int orow = og * OUT_PER_T + o;
        const float bv = sb[orow];
        float v[4];
        #pragma unroll
        for (int q = 0; q < 2; ++q) {
            float lo, hi;
            unpack2(acc[o][q], lo, hi);
            lo += bv; hi += bv;
            if (DO_LRELU) { lo = lrelu(lo); hi = lrelu(hi); }
            v[2 * q] = lo; v[2 * q + 1] = hi;
        }
        *reinterpret_cast<float4*>(sOut + orow * PXT + pixoff) = make_float4(v[0], v[1], v[2], v[3]);
    }
}

__global__ void __launch_bounds__(TPB, 2)
reg1stage_kernel(const float* __restrict__ x,
                 const float* __restrict__ W1g, const float* __restrict__ b1g,
                 const float* __restrict__ W2g, const float* __restrict__ b2g,
                 const float* __restrict__ W3g, const float* __restrict__ b3g,
                 const float* __restrict__ Wr,  const float* __restrict__ br,
                 float* __restrict__ out)
{
    extern __shared__ float smem[];
    const int h   = blockIdx.x;
    const int b   = blockIdx.y;
    const int tid = threadIdx.x;

    float* sW1t = smem + OFF_W1T;
    float* sW2t = smem + OFF_W2T;
    float* sW3t = smem + OFF_W3T;
    float* sb1  = smem + OFF_B1;
    float* sb2  = smem + OFF_B2;
    float* sb3  = smem + OFF_B3;
    float* sx   = smem + OFF_SX;    // [C][PXT]
    float* sy   = smem + OFF_SY;    // [64][PXT], reused Y1 -> Y2 -> cls

    // ---- stage transposed weights + biases for row h ----
    {
        const float* g1 = W1g + h * 4096;
        const float* g2 = W2g + h * 4096;
        #pragma unroll
        for (int i = 0; i < 16; ++i) {
            const int idx = tid + i * TPB;            // 4096
            const int o = idx >> 6, c = idx & 63;
            sW1t[c * WS12 + o] = g1[idx];
            sW2t[c * WS12 + o] = g2[idx];
        }
        #pragma unroll
        for (int i = 0; i < 8; ++i) {
            const int idx = tid + i * TPB;            // 2048
            const int ko = idx >> 6, c = idx & 63;
            sW3t[c * WS3 + ko] = (W3g + h * 2048)[idx];
        }
        if (tid < 64) {
            sb1[tid] = b1g[h * 64 + tid];
            sb2[tid] = b2g[h * 64 + tid];
        }
        if (tid < 32) sb3[tid] = b3g[h * 32 + tid];
    }

    const int cstride = H * W;
    const float* xbase = x + b * C * cstride + h * W;
    const float inv_k = 1.0f / (float)K;
    const int pix_base = (b * H + h) * W;
    const int plane = B * H * W;

    // warp-owns-pixels layout
    const int wsid   = tid >> 5;          // warp 0..7 -> pixel slice of 16
    const int lane   = tid & 31;
    const int og     = lane >> 2;         // 8 output groups
    const int pq     = lane & 3;          // 4 pixel sub-groups of 4 px
    const int pixoff = wsid * 16 + pq * 4;

    for (int wt = 0; wt < WT; ++wt) {
        const int w0 = wt * PXT;
        __syncthreads();                   // prev tile fully consumed

        // ---- stage x tile [C][PXT], coalesced ----
        {
            const int px = tid & (PXT - 1);        // 0..127
            const int ch = tid >> 7;               // 0..1
            const int w = min(w0 + px, W - 1);
            #pragma unroll
            for (int c = ch; c < C; c += 2)
                sx[c * PXT + px] = __ldg(xbase + c * cstride + w);
        }
        __syncthreads();

        // ---- layer 1 ----
        {
            unsigned long long acc[8][2];
            gemm_ffma2<8>(sW1t, WS12, sx, og, pixoff, acc);
            epilogue_store<8, true>(acc, sb1, sy, og, pixoff);
        }
        __syncthreads();

        // ---- layer 2 (in-place on sy after full read) ----
        {
            unsigned long long acc[8][2];
            gemm_ffma2<8>(sW2t, WS12, sy, og, pixoff, acc);
            __syncthreads();
            epilogue_store<8, true>(acc, sb2, sy, og, pixoff);
        }
        __syncthreads();

        // ---- layer 3: 32 outputs (lrelu skipped: monotone for argmax) ----
        {
            unsigned long long acc[4][2];
            gemm_ffma2<4>(sW3t, WS3, sy, og, pixoff, acc);
            __syncthreads();
            epilogue_store<4, false>(acc, sb3, sy, og, pixoff);
        }
        __syncthreads();

        // ---- argmax + class-conditioned linear: 2 threads per pixel ----
        {
            const int px   = tid >> 1;             // 0..127
            const int half = tid & 1;
            const int w = w0 + px;
            if (w < W) {
                float best = -3.402823466e38f;
                int bk = 0;
                #pragma unroll
                for (int k = 0; k < K; ++k) {      // ascending, strict > => first max
                    const float s = sy[k * PXT + px];
                    if (s > best) { best = s; bk = k; }
                }

                const int flat = h * K + bk;
                const float2* wr = reinterpret_cast<const float2*>(Wr + (size_t)flat * (C * 2))
                                   + half * 32;
                const float* sxp = sx + px + half * 32 * PXT;
                float r0 = 0.0f, r1 = 0.0f;
                #pragma unroll
                for (int c = 0; c < 32; ++c) {
                    const float  xv = sxp[c * PXT];
                    const float2 wv = __ldg(wr + c);
                    r0 = fmaf(xv, wv.x, r0);
                    r1 = fmaf(xv, wv.y, r1);
                }
                r0 += __shfl_xor_sync(0xFFFFFFFFu, r0, 1);
                r1 += __shfl_xor_sync(0xFFFFFFFFu, r1, 1);

                if (half == 0) {
                    const float2 bv = __ldg(reinterpret_cast<const float2*>(br) + flat);
                    const float reg0 = lrelu(r0 + bv.x);
                    const float reg1 = lrelu(r1 + bv.y);
                    const int pix = pix_base + w;
                    out[pix]         = ((float)flat + reg0) * inv_k;
                    out[plane + pix] = lrelu(reg1);
                }
            }
        }
    }
}

extern "C" void kernel_launch(void* const* d_in, const int* in_sizes, int n_in,
                              void* d_out, int out_size)
{
    const float* x  = (const float*)d_in[0];
    const float* W1 = (const float*)d_in[1];
    const float* b1 = (const float*)d_in[2];
    const float* W2 = (const float*)d_in[3];
    const float* b2 = (const float*)d_in[4];
    const float* W3 = (const float*)d_in[5];
    const float* b3 = (const float*)d_in[6];
    const float* Wr = (const float*)d_in[7];
    const float* br = (const float*)d_in[8];
    float* out = (float*)d_out;

    const size_t smem_bytes = (size_t)SMEM_FLOATS * sizeof(float);  // 110208 B
    cudaFuncSetAttribute(reg1stage_kernel,
                         cudaFuncAttributeMaxDynamicSharedMemorySize, (int)smem_bytes);

    dim3 grid(H, B);
    reg1stage_kernel<<<grid, TPB, smem_bytes>>>(x, W1, b1, W2, b2, W3, b3, Wr, br, out);
}